// round 4
// baseline (speedup 1.0000x reference)
#include <cuda_runtime.h>
#include <cuda_bf16.h>

// Problem constants (match reference)
#define BB 256
#define SS 8192
#define NPOS (BB * SS)          // 2,097,152
#define IGNORE_LBL (-100)

// Persistent accumulators (no device allocation allowed)
__device__ double g_acc[3];                 // [0]=aspect focal sum, [1]=opinion focal sum, [2]=boundary bce sum
__device__ unsigned long long g_cnt[2];     // valid counts: aspect, opinion

__global__ void zero_acc_kernel() {
    if (threadIdx.x < 3) g_acc[threadIdx.x] = 0.0;
    if (threadIdx.x < 2) g_cnt[threadIdx.x] = 0ull;
}

__device__ __forceinline__ float warp_sum_f(float v) {
    #pragma unroll
    for (int o = 16; o > 0; o >>= 1) v += __shfl_down_sync(0xffffffffu, v, o);
    return v;
}
__device__ __forceinline__ unsigned warp_sum_u(unsigned v) {
    #pragma unroll
    for (int o = 16; o > 0; o >>= 1) v += __shfl_down_sync(0xffffffffu, v, o);
    return v;
}

// Focal loss for a 3-class position. Returns fl contribution; sets valid.
__device__ __forceinline__ float focal3(float l0, float l1, float l2, int lab,
                                        float gamma_unused, unsigned& valid_cnt) {
    if (lab == IGNORE_LBL) return 0.0f;
    valid_cnt += 1u;
    float m  = fmaxf(l0, fmaxf(l1, l2));
    float e0 = __expf(l0 - m);
    float e1 = __expf(l1 - m);
    float e2 = __expf(l2 - m);
    float sum = e0 + e1 + e2;
    float inv = __frcp_rn(sum);
    float ey  = (lab == 0) ? e0 : ((lab == 1) ? e1 : e2);
    float ly  = (lab == 0) ? l0 : ((lab == 1) ? l1 : l2);
    float ce  = (m + __logf(sum)) - ly;     // lse - l[y]
    float pt  = ey * inv;                    // exp(-ce), computed exactly
    float omp = 1.0f - pt;
    return omp * omp * ce;                   // gamma = 2
}

__device__ __forceinline__ float bce_logit(float z, float y) {
    return fmaxf(z, 0.0f) - z * y + log1pf(__expf(-fabsf(z)));
}

__global__ __launch_bounds__(256)
void triple_align_main_kernel(const float*  __restrict__ al,   // aspect logits  [B,S,3]
                              const float*  __restrict__ ol,   // opinion logits [B,S,3]
                              const float*  __restrict__ bl,   // boundary logits [B,S,2]
                              const int*    __restrict__ alab, // aspect labels  [B,S]
                              const int*    __restrict__ olab) // opinion labels [B,S]
{
    float sa = 0.0f, so = 0.0f, sb = 0.0f;
    unsigned ca = 0u, co = 0u;

    const int stride = gridDim.x * blockDim.x;
    for (int p = blockIdx.x * blockDim.x + threadIdx.x; p < NPOS; p += stride) {
        const int s = p & (SS - 1);
        const int la = alab[p];
        const int lo = olab[p];
        const bool last = (s == SS - 1);
        const int la_n = last ? -1 : __ldg(&alab[p + 1]);
        const int lo_n = last ? -1 : __ldg(&olab[p + 1]);

        // aspect focal
        {
            const float* a = al + 3 * (size_t)p;
            sa += focal3(a[0], a[1], a[2], la, 2.0f, ca);
        }
        // opinion focal
        {
            const float* o = ol + 3 * (size_t)p;
            so += focal3(o[0], o[1], o[2], lo, 2.0f, co);
        }
        // boundary labels: start = (lab==1) OR'd; end = (lab==2 && next!=2) OR'd
        {
            const float y0 = ((la == 1) || (lo == 1)) ? 1.0f : 0.0f;
            const float y1 = (((la == 2) && (la_n != 2)) ||
                              ((lo == 2) && (lo_n != 2))) ? 1.0f : 0.0f;
            const float2 z = reinterpret_cast<const float2*>(bl)[p];
            sb += bce_logit(z.x, y0) + bce_logit(z.y, y1);
        }
    }

    // Block reduction: 8 warps
    __shared__ float sh_a[8], sh_o[8], sh_b[8];
    __shared__ unsigned sh_ca[8], sh_co[8];
    const int wid = threadIdx.x >> 5;
    const int lid = threadIdx.x & 31;

    sa = warp_sum_f(sa);
    so = warp_sum_f(so);
    sb = warp_sum_f(sb);
    ca = warp_sum_u(ca);
    co = warp_sum_u(co);
    if (lid == 0) { sh_a[wid] = sa; sh_o[wid] = so; sh_b[wid] = sb; sh_ca[wid] = ca; sh_co[wid] = co; }
    __syncthreads();
    if (wid == 0) {
        float va = (lid < 8) ? sh_a[lid] : 0.0f;
        float vo = (lid < 8) ? sh_o[lid] : 0.0f;
        float vb = (lid < 8) ? sh_b[lid] : 0.0f;
        unsigned uca = (lid < 8) ? sh_ca[lid] : 0u;
        unsigned uco = (lid < 8) ? sh_co[lid] : 0u;
        va = warp_sum_f(va); vo = warp_sum_f(vo); vb = warp_sum_f(vb);
        uca = warp_sum_u(uca); uco = warp_sum_u(uco);
        if (lid == 0) {
            atomicAdd(&g_acc[0], (double)va);
            atomicAdd(&g_acc[1], (double)vo);
            atomicAdd(&g_acc[2], (double)vb);
            atomicAdd(&g_cnt[0], (unsigned long long)uca);
            atomicAdd(&g_cnt[1], (unsigned long long)uco);
        }
    }
}

__global__ __launch_bounds__(256)
void finalize_kernel(const float* __restrict__ sl,   // sentiment logits [B,3]
                     const int*   __restrict__ slab, // sentiment labels [B]
                     float* __restrict__ out)
{
    const int b = threadIdx.x;   // B == 256 == blockDim.x
    float ce = 0.0f;
    unsigned v = 0u;
    {
        const int lab = slab[b];
        if (lab != IGNORE_LBL) {
            v = 1u;
            const float l0 = sl[3 * b + 0];
            const float l1 = sl[3 * b + 1];
            const float l2 = sl[3 * b + 2];
            const float m  = fmaxf(l0, fmaxf(l1, l2));
            const float sum = __expf(l0 - m) + __expf(l1 - m) + __expf(l2 - m);
            const float ly  = (lab == 0) ? l0 : ((lab == 1) ? l1 : l2);
            ce = (m + __logf(sum)) - ly;
        }
    }

    __shared__ float sh_ce[8];
    __shared__ unsigned sh_v[8];
    const int wid = threadIdx.x >> 5;
    const int lid = threadIdx.x & 31;
    ce = warp_sum_f(ce);
    v  = warp_sum_u(v);
    if (lid == 0) { sh_ce[wid] = ce; sh_v[wid] = v; }
    __syncthreads();
    if (threadIdx.x == 0) {
        float ce_sum = 0.0f;
        unsigned v_sum = 0u;
        #pragma unroll
        for (int i = 0; i < 8; i++) { ce_sum += sh_ce[i]; v_sum += sh_v[i]; }

        const double na = (double)g_cnt[0];
        const double no = (double)g_cnt[1];
        const float aspect_loss  = (g_cnt[0] > 0) ? (float)(g_acc[0] / (na < 1.0 ? 1.0 : na)) : 0.0f;
        const float opinion_loss = (g_cnt[1] > 0) ? (float)(g_acc[1] / (no < 1.0 ? 1.0 : no)) : 0.0f;
        const float ns = (float)v_sum;
        const float sentiment_loss = ce_sum / fmaxf(ns, 1.0f);
        const float boundary_loss  = (float)(g_acc[2] / (double)(NPOS * 2));

        out[0] = aspect_loss + opinion_loss + sentiment_loss + 0.5f * boundary_loss;
    }
}

extern "C" void kernel_launch(void* const* d_in, const int* in_sizes, int n_in,
                              void* d_out, int out_size) {
    const float* aspect_logits    = (const float*)d_in[0];
    const float* opinion_logits   = (const float*)d_in[1];
    const float* sentiment_logits = (const float*)d_in[2];
    const float* boundary_logits  = (const float*)d_in[3];
    const int*   aspect_labels    = (const int*)d_in[4];
    const int*   opinion_labels   = (const int*)d_in[5];
    const int*   sentiment_labels = (const int*)d_in[6];
    float* out = (float*)d_out;

    zero_acc_kernel<<<1, 32>>>();
    // 2048 blocks x 256 thr: 524288 threads, 4 positions each (grid-stride)
    triple_align_main_kernel<<<2048, 256>>>(aspect_logits, opinion_logits,
                                            boundary_logits,
                                            aspect_labels, opinion_labels);
    finalize_kernel<<<1, 256>>>(sentiment_logits, sentiment_labels, out);
}